// round 16
// baseline (speedup 1.0000x reference)
#include <cuda_runtime.h>
#include <cuda_fp16.h>
#include <cstdint>

typedef unsigned long long ull;

#define KKn  9
#define Bn   8
#define Cn   256
#define Hn   96
#define Wn   96
#define On   256
#define HWn  (Hn*Wn)          // 9216
#define KDIM (Cn*KKn)         // 2304

// ---- main mma kernel ----
#define NT    256
#define TPIX  64              // pixels per CTA
#define CH    64              // K-chunk (channels)
#define NCH2  (KDIM/CH)       // 36
#define NCOORD (TPIX*KKn)     // 576

// sub-tile strides (stagger +64B keeps gather STS conflict-free)
#define WSUB  16448u          // w sub-tile [256][32ch] + 64
#define SSUB  4160u           // s sub-tile [64][32ch] + 64
#define WBUFB (2u*WSUB)       // 32896
#define SBUFB (2u*SSUB)       // 8320

#define WH0   0u
#define WH1   32896u
#define SH0   65792u
#define SH1   74112u
#define CO_B  82432u
#define SMEM_BYTES (82432 + 3*NCOORD*4)   // 89344 -> 2 blocks/SM

// ---- offset mma kernel (1-pass fp16, unchanged from R15) ----
#define ONT   128
#define OTP   128
#define OAH0  0u
#define OAH1  2048u
#define OBH0  4096u
#define OBH1  12288u
#define OV_B  20480u
#define OVSTR 132
#define OSMEM (20480 + 28*OVSTR*4)        // 35264

// ---------------- scratch ----------------
__device__ __half g_xth[Bn*HWn*Cn];      // x transposed to NHWC, fp16
__device__ float g_py [Bn*KKn*HWn];
__device__ float g_px [Bn*KKn*HWn];
__device__ float g_msk[Bn*KKn*HWn];
__device__ __half g_wh [On*KDIM];        // main w fp16 [o][kk*256+c]
__device__ __half g_woh[32*KDIM];        // offset w fp16 [o pad32][kk*256+c]
__device__ float g_bnA[On];
__device__ float g_bnB[On];

// ---------------- helpers ----------------
__device__ __forceinline__ uint32_t smem_u32(const void* p) {
    return (uint32_t)__cvta_generic_to_shared(p);
}
__device__ __forceinline__ void cp16(uint32_t dst, const void* src) {
    asm volatile("cp.async.cg.shared.global [%0], [%1], 16;" :: "r"(dst), "l"(src));
}
__device__ __forceinline__ void cp16z(uint32_t dst, const void* src, uint32_t sz) {
    asm volatile("cp.async.cg.shared.global [%0], [%1], 16, %2;"
        :: "r"(dst), "l"(src), "r"(sz));
}
#define CP_COMMIT()  asm volatile("cp.async.commit_group;")
#define CP_WAIT0()   asm volatile("cp.async.wait_group 0;")

__device__ __forceinline__ void ldsm4(uint32_t* r, uint32_t addr) {
    asm volatile("ldmatrix.sync.aligned.m8n8.x4.shared.b16 {%0,%1,%2,%3}, [%4];"
        : "=r"(r[0]), "=r"(r[1]), "=r"(r[2]), "=r"(r[3]) : "r"(addr));
}
__device__ __forceinline__ void mma_h(float* d, const uint32_t* a, uint32_t b0, uint32_t b1) {
    asm volatile("mma.sync.aligned.m16n8k16.row.col.f32.f16.f16.f32 "
        "{%0,%1,%2,%3}, {%4,%5,%6,%7}, {%8,%9}, {%0,%1,%2,%3};"
        : "+f"(d[0]), "+f"(d[1]), "+f"(d[2]), "+f"(d[3])
        : "r"(a[0]), "r"(a[1]), "r"(a[2]), "r"(a[3]), "r"(b0), "r"(b1));
}

// ---------------- prep ----------------
__global__ void prep_kernel(const float* __restrict__ w_off,
                            const float* __restrict__ w_dcn,
                            const float* __restrict__ b_dcn,
                            const float* __restrict__ gamma,
                            const float* __restrict__ beta,
                            const float* __restrict__ rmean,
                            const float* __restrict__ rvar) {
    int t = blockIdx.x * blockDim.x + threadIdx.x;
    int stride = gridDim.x * blockDim.x;
    for (int i = t; i < On*KDIM; i += stride) {
        int K = i % KDIM; int o = i / KDIM;
        int kk = K / Cn;  int c = K % Cn;
        g_wh[i] = __float2half_rn(w_dcn[(o*Cn + c)*KKn + kk]);
    }
    for (int i = t; i < 32*KDIM; i += stride) {
        int K = i % KDIM; int o = i / KDIM;
        int kk = K / Cn;  int c = K % Cn;
        float v = (o < 27) ? w_off[(o*Cn + c)*KKn + kk] : 0.f;
        g_woh[i] = __float2half_rn(v);
    }
    if (t < On) {
        float inv = rsqrtf(rvar[t] + 1e-5f);
        float A = gamma[t] * inv;
        g_bnA[t] = A;
        g_bnB[t] = (b_dcn[t] - rmean[t]) * A + beta[t];
    }
}

// ---------------- NCHW fp32 -> NHWC fp16 transpose ----------------
__global__ void transpose_kernel(const float* __restrict__ x) {
    __shared__ float tile[32][33];
    int bh = blockIdx.z;
    int c0 = blockIdx.y * 32;
    int w0 = blockIdx.x * 32;
    int b = bh / Hn; int h = bh % Hn;
    for (int i = threadIdx.y; i < 32; i += 8)
        tile[i][threadIdx.x] = x[((b*Cn + c0 + i)*Hn + h)*Wn + w0 + threadIdx.x];
    __syncthreads();
    for (int i = threadIdx.y; i < 32; i += 8)
        g_xth[((size_t)(b*Hn + h)*Wn + w0 + i)*Cn + c0 + threadIdx.x] =
            __float2half_rn(tile[threadIdx.x][i]);
}

// ---------------- offset conv via fp16 1-pass mma (R15, unchanged) ----------------
__global__ __launch_bounds__(ONT) void offset_mma_kernel(const float* __restrict__ b_off) {
    extern __shared__ char smc[];
    uint32_t sb = smem_u32(smc);
    float* ov = (float*)(smc + OV_B);

    int tid  = threadIdx.x;
    int lane = tid & 31;
    int wid  = tid >> 5;
    int pixb = blockIdx.x * OTP;
    int b    = pixb / HWn;
    int hwb  = pixb % HWn;
    const __half* xtbh = g_xth + (size_t)b * (HWn*Cn);

    auto stage = [&](int q) {
        uint32_t ab = (q & 1) ? OAH1 : OAH0;
        uint32_t bb = (q & 1) ? OBH1 : OBH0;
        {
            int row = tid >> 2, quad = tid & 3;
            cp16(sb + ab + (uint32_t)row*64u + (uint32_t)((quad ^ ((row>>1)&3)) << 4),
                 g_woh + (size_t)row*KDIM + q*32 + quad*8);
        }
        int kk = q >> 3;
        int c32 = (q & 7) * 32;
        int dy = kk/3 - 1, dx = kk%3 - 1;
        #pragma unroll
        for (int i = 0; i < 4; i++) {
            int t = i*ONT + tid;
            int p = t >> 2, quad = t & 3;
            int hw = hwb + p;
            int h = hw / Wn, w = hw % Wn;
            int y = h + dy, x = w + dx;
            bool ok = ((unsigned)y < (unsigned)Hn) && ((unsigned)x < (unsigned)Wn);
            const __half* src = ok ? (xtbh + (((y*Wn + x) << 8) + c32 + quad*8)) : xtbh;
            uint32_t dst = sb + bb + (uint32_t)p*64u + (uint32_t)((quad ^ ((p>>1)&3)) << 4);
            cp16z(dst, src, ok ? 16u : 0u);
        }
        CP_COMMIT();
    };

    stage(0);

    int pb = wid * 32;
    float acc[2][4][4];
    #pragma unroll
    for (int mt = 0; mt < 2; mt++)
        #pragma unroll
        for (int nt = 0; nt < 4; nt++)
            #pragma unroll
            for (int e = 0; e < 4; e++) acc[mt][nt][e] = 0.f;

    #pragma unroll 1
    for (int q = 0; q < 72; q++) {
        int buf = q & 1;
        bool more = (q + 1 < 72);
        CP_WAIT0();
        __syncthreads();

        if (more) stage(q+1);

        uint32_t ab = sb + (buf ? OAH1 : OAH0);
        uint32_t bb = sb + (buf ? OBH1 : OBH0);
        #pragma unroll
        for (int ks = 0; ks < 2; ks++) {
            uint32_t bh[2][4];
            #pragma unroll
            for (int np = 0; np < 2; np++) {
                int p = pb + np*16 + (lane & 7) + ((lane >> 4) << 3);
                int u = ks*2 + ((lane >> 3) & 1);
                uint32_t bd = bb + (uint32_t)p*64u + (uint32_t)((u ^ ((p>>1)&3)) << 4);
                ldsm4(bh[np], bd);
            }
            #pragma unroll
            for (int mt = 0; mt < 2; mt++) {
                int o = mt*16 + (lane & 15);
                int u = ks*2 + (lane >> 4);
                uint32_t ad = ab + (uint32_t)o*64u + (uint32_t)((u ^ ((o>>1)&3)) << 4);
                uint32_t ah[4];
                ldsm4(ah, ad);
                #pragma unroll
                for (int np = 0; np < 2; np++)
                    #pragma unroll
                    for (int hf = 0; hf < 2; hf++)
                        mma_h(acc[mt][np*2+hf], ah, bh[np][hf*2], bh[np][hf*2+1]);
            }
        }
    }
    __syncthreads();

    #pragma unroll
    for (int mt = 0; mt < 2; mt++) {
        int o0 = mt*16 + (lane >> 2);
        int o1 = o0 + 8;
        #pragma unroll
        for (int nt = 0; nt < 4; nt++) {
            int p = pb + nt*8 + (lane & 3)*2;
            if (o0 < 27) {
                ov[o0*OVSTR + p]   = acc[mt][nt][0];
                ov[o0*OVSTR + p+1] = acc[mt][nt][1];
            }
            if (o1 < 27) {
                ov[o1*OVSTR + p]   = acc[mt][nt][2];
                ov[o1*OVSTR + p+1] = acc[mt][nt][3];
            }
        }
    }
    __syncthreads();

    {
        int p = tid;
        int hw = hwb + p;
        int h = hw / Wn, w = hw % Wn;
        #pragma unroll
        for (int k = 0; k < KKn; k++) {
            float py = ov[(2*k)*OVSTR + p]   + b_off[2*k]   + (float)(h + k/3 - 1);
            float px = ov[(2*k+1)*OVSTR + p] + b_off[2*k+1] + (float)(w + k%3 - 1);
            float mv = ov[(18+k)*OVSTR + p]  + b_off[18+k];
            float mm = 1.f / (1.f + expf(-mv));
            int idx = (b*KKn + k)*HWn + hw;
            g_py[idx] = py; g_px[idx] = px; g_msk[idx] = mm;
        }
    }
}

// ---------------- main: fp16 1-pass mma, K-chunk 64, line-aligned gather ----------------
__device__ __forceinline__ uint4 corner_ldh(const __half* __restrict__ xtbh, int y, int x, int c) {
    if ((unsigned)y < (unsigned)Hn && (unsigned)x < (unsigned)Wn)
        return *(const uint4*)(xtbh + (((y*Wn + x) << 8) + c));
    return make_uint4(0u, 0u, 0u, 0u);
}

__global__ __launch_bounds__(NT, 2) void main_kernel(float* __restrict__ out) {
    extern __shared__ char smc[];
    uint32_t sb = smem_u32(smc);
    float* spy = (float*)(smc + CO_B);
    float* spx = spy + NCOORD;
    float* smk = spx + NCOORD;

    int tid  = threadIdx.x;
    int lane = tid & 31;
    int wid  = tid >> 5;
    int pixb = blockIdx.x * TPIX;
    int b    = pixb / HWn;
    int hwb  = pixb % HWn;

    for (int i = tid; i < NCOORD; i += NT) {
        int p = i / KKn, k = i % KKn;
        int gi = (b*KKn + k)*HWn + hwb + p;
        spy[i] = g_py[gi]; spx[i] = g_px[gi]; smk[i] = g_msk[gi];
    }
    __syncthreads();

    const __half* xtbh = g_xth + (size_t)b * (HWn*Cn);

    int gp8 = tid >> 3;        // pixel (task0); task1 pixel = gp8 + 32
    int gg  = tid & 7;         // 16B channel group (0..7 across 64 ch)
    // STS offsets (conflict-free by sub-tile stagger)
    uint32_t sts_sub = (uint32_t)(gg >> 2) * SSUB;
    uint32_t sts_seg0 = (uint32_t)(((gg & 3) ^ ((gp8 >> 1) & 3)) << 4);
    uint32_t sts_seg1 = (uint32_t)(((gg & 3) ^ (((gp8 + 32) >> 1) & 3)) << 4);
    uint32_t sts_off0 = sts_sub + (uint32_t)gp8*64u + sts_seg0;
    uint32_t sts_off1 = sts_sub + (uint32_t)(gp8 + 32)*64u + sts_seg1;

    auto cpW = [&](int q) {
        uint32_t wb = (q & 1) ? WH1 : WH0;
        #pragma unroll
        for (int i = 0; i < 8; i++) {
            int id = i*NT + tid;
            int o = id >> 3;
            int g = id & 7;
            const __half* src = g_wh + (size_t)o*KDIM + q*CH + g*8;
            uint32_t dst = sb + wb + (uint32_t)(g >> 2)*WSUB + (uint32_t)o*64u
                         + (uint32_t)(((g & 3) ^ ((o >> 1) & 3)) << 4);
            cp16(dst, src);
        }
        CP_COMMIT();
    };

    __half2 W00, W01, W10, W11, MMh;
    auto load_state = [&](int p, int kkn) {
        float py = spy[p*KKn + kkn], px = spx[p*KKn + kkn], mm = smk[p*KKn + kkn];
        float fy = floorf(py), fx = floorf(px);
        int y0 = (int)fy, x0 = (int)fx;
        float wy = py - fy, wx = px - fx;
        W00 = __float2half2_rn((1.f-wy)*(1.f-wx));
        W01 = __float2half2_rn((1.f-wy)*wx);
        W10 = __float2half2_rn(wy*(1.f-wx));
        W11 = __float2half2_rn(wy*wx);
        MMh = __float2half2_rn(mm);
        return make_int2(y0, x0);
    };
    auto interp_h2 = [&](uint4 C0, uint4 C1, uint4 C2, uint4 C3) -> uint4 {
        const __half2* c0 = (const __half2*)&C0;
        const __half2* c1 = (const __half2*)&C1;
        const __half2* c2 = (const __half2*)&C2;
        const __half2* c3 = (const __half2*)&C3;
        uint4 res;
        __half2* rp = (__half2*)&res;
        #pragma unroll
        for (int j = 0; j < 4; j++) {
            __half2 a = __hmul2(c0[j], W00);
            a = __hfma2(c1[j], W01, a);
            a = __hfma2(c2[j], W10, a);
            a = __hfma2(c3[j], W11, a);
            rp[j] = __hmul2(a, MMh);
        }
        return res;
    };

    // ---- prologue: w chunk 0 + full gather of s chunk 0 ----
    {
        cpW(0);
        int cb = gg*8;   // chunk 0: cpos = 0
        int2 yx = load_state(gp8, 0);
        uint4 C0 = corner_ldh(xtbh, yx.x,   yx.y,   cb);
        uint4 C1 = corner_ldh(xtbh, yx.x,   yx.y+1, cb);
        uint4 C2 = corner_ldh(xtbh, yx.x+1, yx.y,   cb);
        uint4 C3 = corner_ldh(xtbh, yx.x+1, yx.y+1, cb);
        *(uint4*)(smc + SH0 + sts_off0) = interp_h2(C0, C1, C2, C3);
        yx = load_state(gp8 + 32, 0);
        C0 = corner_ldh(xtbh, yx.x,   yx.y,   cb);
        C1 = corner_ldh(xtbh, yx.x,   yx.y+1, cb);
        C2 = corner_ldh(xtbh, yx.x+1, yx.y,   cb);
        C3 = corner_ldh(xtbh, yx.x+1, yx.y+1, cb);
        *(uint4*)(smc + SH0 + sts_off1) = interp_h2(C0, C1, C2, C3);
    }

    int ob = (wid >> 1) * 64;
    int pb = (wid & 1) * 32;
    float acc[4][4][4];
    #pragma unroll
    for (int mt = 0; mt < 4; mt++)
        #pragma unroll
        for (int nt = 0; nt < 4; nt++)
            #pragma unroll
            for (int e = 0; e < 4; e++) acc[mt][nt][e] = 0.f;

    #pragma unroll 1
    for (int q = 0; q < NCH2; q++) {
        int buf = q & 1;
        bool more = (q + 1 < NCH2);
        int kkn = (q + 1) >> 2;
        int cb  = ((q + 1) & 3) * 64 + gg*8;

        // ---- task0 pre-issue: pixel gp8, chunk q+1 ----
        uint4 C0, C1, C2, C3;
        if (more) {
            int2 yx = load_state(gp8, kkn);
            C0 = corner_ldh(xtbh, yx.x,   yx.y,   cb);
            C1 = corner_ldh(xtbh, yx.x,   yx.y+1, cb);
            C2 = corner_ldh(xtbh, yx.x+1, yx.y,   cb);
            C3 = corner_ldh(xtbh, yx.x+1, yx.y+1, cb);
        }

        CP_WAIT0();        // w chunk q landed
        __syncthreads();   // visible; all warps done with buffers of chunk q-1

        if (more) cpW(q+1);

        uint32_t whb = sb + (buf ? WH1 : WH0);
        uint32_t shb = sb + (buf ? SH1 : SH0);
        uint32_t sdst_b = ((q+1) & 1) ? SH1 : SH0;

        // ---- MMA ks2 = 0,1 ----
        #pragma unroll
        for (int ks2 = 0; ks2 < 2; ks2++) {
            uint32_t stw = (uint32_t)(ks2 >> 1) * WSUB;   // 0
            uint32_t sts = (uint32_t)(ks2 >> 1) * SSUB;   // 0
            int uu = (ks2 & 1) * 2;
            uint32_t bh[2][4];
            #pragma unroll
            for (int np = 0; np < 2; np++) {
                int p = pb + np*16 + (lane & 7) + ((lane >> 4) << 3);
                int u = uu + ((lane >> 3) & 1);
                ldsm4(bh[np], shb + sts + (uint32_t)p*64u + (uint32_t)((u ^ ((p>>1)&3)) << 4));
            }
            #pragma unroll
            for (int mt = 0; mt < 4; mt++) {
                int o = ob + mt*16 + (lane & 15);
                int u = uu + (lane >> 4);
                uint32_t ah[4];
                ldsm4(ah, whb + stw + (uint32_t)o*64u + (uint32_t)((u ^ ((o>>1)&3)) << 4));
                #pragma unroll
                for (int np = 0; np < 2; np++)
                    #pragma unroll
                    for (int hf = 0; hf < 2; hf++)
                        mma_h(acc[mt][np*2+hf], ah, bh[np][hf*2], bh[np][hf*2+1]);
            }
        }

        // ---- finish task0; pre-issue task1 ----
        if (more) {
            *(uint4*)(smc + sdst_b + sts_off0) = interp_h2(C0, C1, C2, C3);
            int2 yx = load_state(gp8 + 32, kkn);
            C0 = corner_ldh(xtbh, yx.x,   yx.y,   cb);
            C1 = corner_ldh(xtbh, yx.x,   yx.y+1, cb);
            C2 = corner_ldh(xtbh, yx.x+1, yx.y,   cb);
            C3 = corner_ldh(xtbh, yx.x+1, yx.y+1, cb);
        }

        // ---- MMA ks2 = 2,3 ----
        #pragma unroll
        for (int ks2 = 2; ks2 < 4; ks2++) {
            uint32_t stw = (uint32_t)(ks2 >> 1) * WSUB;
            uint32_t sts = (uint32_t)(ks2 >> 1) * SSUB;
            int uu = (ks2 & 1) * 2;
            uint32_t bh[2][4];
            #pragma unroll
            for (int np = 0; np < 2; np++) {
                int p = pb + np*16 + (lane & 7) + ((lane >> 4) << 3);
                int u = uu + ((lane >> 3) & 1);
                ldsm4(bh[np], shb + sts + (uint32_t)p*64u + (uint32_t)((u ^ ((p>>1)&3)) << 4));
            }
            #pragma unroll
            for (int mt = 0; mt < 4; mt++) {
                int o = ob + mt*16 + (lane & 15);
                int u = uu + (lane >> 4);
                uint32_t ah[4];
                ldsm4(ah, whb + stw + (uint32_t)o*64u + (uint32_t)((u ^ ((o>>1)&3)) << 4));
                #pragma unroll
                for (int np = 0; np < 2; np++)
                    #pragma unroll
                    for (int hf = 0; hf < 2; hf++)
                        mma_h(acc[mt][np*2+hf], ah, bh[np][hf*2], bh[np][hf*2+1]);
            }
        }

        // ---- finish task1 ----
        if (more) {
            *(uint4*)(smc + sdst_b + sts_off1) = interp_h2(C0, C1, C2, C3);
        }
    }

    // ---- epilogue: BN + ReLU ----
    int tg = lane & 3, g = lane >> 2;
    #pragma unroll
    for (int mt = 0; mt < 4; mt++) {
        int o0 = ob + mt*16 + g;
        int o1 = o0 + 8;
        float A0 = g_bnA[o0], B0 = g_bnB[o0];
        float A1 = g_bnA[o1], B1 = g_bnB[o1];
        float* r0 = out + ((size_t)(b*On + o0))*HWn + hwb;
        float* r1 = out + ((size_t)(b*On + o1))*HWn + hwb;
        #pragma unroll
        for (int nt = 0; nt < 4; nt++) {
            int p0 = pb + nt*8 + tg*2;
            float2 v0, v1;
            v0.x = fmaxf(acc[mt][nt][0]*A0 + B0, 0.f);
            v0.y = fmaxf(acc[mt][nt][1]*A0 + B0, 0.f);
            v1.x = fmaxf(acc[mt][nt][2]*A1 + B1, 0.f);
            v1.y = fmaxf(acc[mt][nt][3]*A1 + B1, 0.f);
            *(float2*)(r0 + p0) = v0;
            *(float2*)(r1 + p0) = v1;
        }
    }
}

// ---------------- launch ----------------
extern "C" void kernel_launch(void* const* d_in, const int* in_sizes, int n_in,
                              void* d_out, int out_size) {
    const float* x      = (const float*)d_in[0];
    const float* w_off  = (const float*)d_in[1];
    const float* b_off  = (const float*)d_in[2];
    const float* w_dcn  = (const float*)d_in[3];
    const float* b_dcn  = (const float*)d_in[4];
    const float* gamma  = (const float*)d_in[5];
    const float* beta   = (const float*)d_in[6];
    const float* rmean  = (const float*)d_in[7];
    const float* rvar   = (const float*)d_in[8];
    float* out = (float*)d_out;

    cudaFuncSetAttribute(main_kernel, cudaFuncAttributeMaxDynamicSharedMemorySize, SMEM_BYTES);
    cudaFuncSetAttribute(main_kernel, cudaFuncAttributePreferredSharedMemoryCarveout, 100);
    cudaFuncSetAttribute(offset_mma_kernel, cudaFuncAttributeMaxDynamicSharedMemorySize, OSMEM);

    prep_kernel<<<256, 256>>>(w_off, w_dcn, b_dcn, gamma, beta, rmean, rvar);

    dim3 tgrid(Wn/32, Cn/32, Bn*Hn);
    transpose_kernel<<<tgrid, dim3(32, 8)>>>(x);

    offset_mma_kernel<<<(Bn*HWn)/OTP, ONT, OSMEM>>>(b_off);

    main_kernel<<<(Bn*HWn)/TPIX, NT, SMEM_BYTES>>>(out);
}

// round 17
// speedup vs baseline: 1.0045x; 1.0045x over previous
#include <cuda_runtime.h>
#include <cuda_fp16.h>
#include <cstdint>

typedef unsigned long long ull;

#define KKn  9
#define Bn   8
#define Cn   256
#define Hn   96
#define Wn   96
#define On   256
#define HWn  (Hn*Wn)          // 9216
#define KDIM (Cn*KKn)         // 2304

// ---- main mma kernel ----
#define NT    512
#define TPIX  128             // pixels per CTA
#define CH    64              // K-chunk (channels)
#define NCH2  (KDIM/CH)       // 36
#define NCOORD (TPIX*KKn)     // 1152

// sub-tile strides (stagger +64B keeps gather STS layout consistent)
#define WSUB  16448u          // w sub-tile [256][32ch] + 64
#define SSUB  8256u           // s sub-tile [128][32ch] + 64

#define WH0   0u
#define WH1   32896u
#define SH0   65792u
#define SH1   82304u
#define CO_B  98816u
#define SMEM_BYTES (98816 + 3*NCOORD*4)   // 112,640 -> 1 block/SM (regs bound anyway)

// ---- offset mma kernel (1-pass fp16, unchanged) ----
#define ONT   128
#define OTP   128
#define OAH0  0u
#define OAH1  2048u
#define OBH0  4096u
#define OBH1  12288u
#define OV_B  20480u
#define OVSTR 132
#define OSMEM (20480 + 28*OVSTR*4)        // 35264

// ---------------- scratch ----------------
__device__ __half g_xth[Bn*HWn*Cn];      // x transposed to NHWC, fp16
__device__ float g_py [Bn*KKn*HWn];
__device__ float g_px [Bn*KKn*HWn];
__device__ float g_msk[Bn*KKn*HWn];
__device__ __half g_wh [On*KDIM];        // main w fp16 [o][kk*256+c]
__device__ __half g_woh[32*KDIM];        // offset w fp16 [o pad32][kk*256+c]
__device__ float g_bnA[On];
__device__ float g_bnB[On];

// ---------------- helpers ----------------
__device__ __forceinline__ uint32_t smem_u32(const void* p) {
    return (uint32_t)__cvta_generic_to_shared(p);
}
__device__ __forceinline__ void cp16(uint32_t dst, const void* src) {
    asm volatile("cp.async.cg.shared.global [%0], [%1], 16;" :: "r"(dst), "l"(src));
}
__device__ __forceinline__ void cp16z(uint32_t dst, const void* src, uint32_t sz) {
    asm volatile("cp.async.cg.shared.global [%0], [%1], 16, %2;"
        :: "r"(dst), "l"(src), "r"(sz));
}
#define CP_COMMIT()  asm volatile("cp.async.commit_group;")
#define CP_WAIT0()   asm volatile("cp.async.wait_group 0;")

__device__ __forceinline__ void ldsm4(uint32_t* r, uint32_t addr) {
    asm volatile("ldmatrix.sync.aligned.m8n8.x4.shared.b16 {%0,%1,%2,%3}, [%4];"
        : "=r"(r[0]), "=r"(r[1]), "=r"(r[2]), "=r"(r[3]) : "r"(addr));
}
__device__ __forceinline__ void mma_h(float* d, const uint32_t* a, uint32_t b0, uint32_t b1) {
    asm volatile("mma.sync.aligned.m16n8k16.row.col.f32.f16.f16.f32 "
        "{%0,%1,%2,%3}, {%4,%5,%6,%7}, {%8,%9}, {%0,%1,%2,%3};"
        : "+f"(d[0]), "+f"(d[1]), "+f"(d[2]), "+f"(d[3])
        : "r"(a[0]), "r"(a[1]), "r"(a[2]), "r"(a[3]), "r"(b0), "r"(b1));
}

// ---------------- prep ----------------
__global__ void prep_kernel(const float* __restrict__ w_off,
                            const float* __restrict__ w_dcn,
                            const float* __restrict__ b_dcn,
                            const float* __restrict__ gamma,
                            const float* __restrict__ beta,
                            const float* __restrict__ rmean,
                            const float* __restrict__ rvar) {
    int t = blockIdx.x * blockDim.x + threadIdx.x;
    int stride = gridDim.x * blockDim.x;
    for (int i = t; i < On*KDIM; i += stride) {
        int K = i % KDIM; int o = i / KDIM;
        int kk = K / Cn;  int c = K % Cn;
        g_wh[i] = __float2half_rn(w_dcn[(o*Cn + c)*KKn + kk]);
    }
    for (int i = t; i < 32*KDIM; i += stride) {
        int K = i % KDIM; int o = i / KDIM;
        int kk = K / Cn;  int c = K % Cn;
        float v = (o < 27) ? w_off[(o*Cn + c)*KKn + kk] : 0.f;
        g_woh[i] = __float2half_rn(v);
    }
    if (t < On) {
        float inv = rsqrtf(rvar[t] + 1e-5f);
        float A = gamma[t] * inv;
        g_bnA[t] = A;
        g_bnB[t] = (b_dcn[t] - rmean[t]) * A + beta[t];
    }
}

// ---------------- NCHW fp32 -> NHWC fp16 transpose ----------------
__global__ void transpose_kernel(const float* __restrict__ x) {
    __shared__ float tile[32][33];
    int bh = blockIdx.z;
    int c0 = blockIdx.y * 32;
    int w0 = blockIdx.x * 32;
    int b = bh / Hn; int h = bh % Hn;
    for (int i = threadIdx.y; i < 32; i += 8)
        tile[i][threadIdx.x] = x[((b*Cn + c0 + i)*Hn + h)*Wn + w0 + threadIdx.x];
    __syncthreads();
    for (int i = threadIdx.y; i < 32; i += 8)
        g_xth[((size_t)(b*Hn + h)*Wn + w0 + i)*Cn + c0 + threadIdx.x] =
            __float2half_rn(tile[threadIdx.x][i]);
}

// ---------------- offset conv via fp16 1-pass mma (unchanged) ----------------
__global__ __launch_bounds__(ONT) void offset_mma_kernel(const float* __restrict__ b_off) {
    extern __shared__ char smc[];
    uint32_t sb = smem_u32(smc);
    float* ov = (float*)(smc + OV_B);

    int tid  = threadIdx.x;
    int lane = tid & 31;
    int wid  = tid >> 5;
    int pixb = blockIdx.x * OTP;
    int b    = pixb / HWn;
    int hwb  = pixb % HWn;
    const __half* xtbh = g_xth + (size_t)b * (HWn*Cn);

    auto stage = [&](int q) {
        uint32_t ab = (q & 1) ? OAH1 : OAH0;
        uint32_t bb = (q & 1) ? OBH1 : OBH0;
        {
            int row = tid >> 2, quad = tid & 3;
            cp16(sb + ab + (uint32_t)row*64u + (uint32_t)((quad ^ ((row>>1)&3)) << 4),
                 g_woh + (size_t)row*KDIM + q*32 + quad*8);
        }
        int kk = q >> 3;
        int c32 = (q & 7) * 32;
        int dy = kk/3 - 1, dx = kk%3 - 1;
        #pragma unroll
        for (int i = 0; i < 4; i++) {
            int t = i*ONT + tid;
            int p = t >> 2, quad = t & 3;
            int hw = hwb + p;
            int h = hw / Wn, w = hw % Wn;
            int y = h + dy, x = w + dx;
            bool ok = ((unsigned)y < (unsigned)Hn) && ((unsigned)x < (unsigned)Wn);
            const __half* src = ok ? (xtbh + (((y*Wn + x) << 8) + c32 + quad*8)) : xtbh;
            uint32_t dst = sb + bb + (uint32_t)p*64u + (uint32_t)((quad ^ ((p>>1)&3)) << 4);
            cp16z(dst, src, ok ? 16u : 0u);
        }
        CP_COMMIT();
    };

    stage(0);

    int pb = wid * 32;
    float acc[2][4][4];
    #pragma unroll
    for (int mt = 0; mt < 2; mt++)
        #pragma unroll
        for (int nt = 0; nt < 4; nt++)
            #pragma unroll
            for (int e = 0; e < 4; e++) acc[mt][nt][e] = 0.f;

    #pragma unroll 1
    for (int q = 0; q < 72; q++) {
        int buf = q & 1;
        bool more = (q + 1 < 72);
        CP_WAIT0();
        __syncthreads();

        if (more) stage(q+1);

        uint32_t ab = sb + (buf ? OAH1 : OAH0);
        uint32_t bb = sb + (buf ? OBH1 : OBH0);
        #pragma unroll
        for (int ks = 0; ks < 2; ks++) {
            uint32_t bh[2][4];
            #pragma unroll
            for (int np = 0; np < 2; np++) {
                int p = pb + np*16 + (lane & 7) + ((lane >> 4) << 3);
                int u = ks*2 + ((lane >> 3) & 1);
                uint32_t bd = bb + (uint32_t)p*64u + (uint32_t)((u ^ ((p>>1)&3)) << 4);
                ldsm4(bh[np], bd);
            }
            #pragma unroll
            for (int mt = 0; mt < 2; mt++) {
                int o = mt*16 + (lane & 15);
                int u = ks*2 + (lane >> 4);
                uint32_t ad = ab + (uint32_t)o*64u + (uint32_t)((u ^ ((o>>1)&3)) << 4);
                uint32_t ah[4];
                ldsm4(ah, ad);
                #pragma unroll
                for (int np = 0; np < 2; np++)
                    #pragma unroll
                    for (int hf = 0; hf < 2; hf++)
                        mma_h(acc[mt][np*2+hf], ah, bh[np][hf*2], bh[np][hf*2+1]);
            }
        }
    }
    __syncthreads();

    #pragma unroll
    for (int mt = 0; mt < 2; mt++) {
        int o0 = mt*16 + (lane >> 2);
        int o1 = o0 + 8;
        #pragma unroll
        for (int nt = 0; nt < 4; nt++) {
            int p = pb + nt*8 + (lane & 3)*2;
            if (o0 < 27) {
                ov[o0*OVSTR + p]   = acc[mt][nt][0];
                ov[o0*OVSTR + p+1] = acc[mt][nt][1];
            }
            if (o1 < 27) {
                ov[o1*OVSTR + p]   = acc[mt][nt][2];
                ov[o1*OVSTR + p+1] = acc[mt][nt][3];
            }
        }
    }
    __syncthreads();

    {
        int p = tid;
        int hw = hwb + p;
        int h = hw / Wn, w = hw % Wn;
        #pragma unroll
        for (int k = 0; k < KKn; k++) {
            float py = ov[(2*k)*OVSTR + p]   + b_off[2*k]   + (float)(h + k/3 - 1);
            float px = ov[(2*k+1)*OVSTR + p] + b_off[2*k+1] + (float)(w + k%3 - 1);
            float mv = ov[(18+k)*OVSTR + p]  + b_off[18+k];
            float mm = 1.f / (1.f + expf(-mv));
            int idx = (b*KKn + k)*HWn + hw;
            g_py[idx] = py; g_px[idx] = px; g_msk[idx] = mm;
        }
    }
}

// ---------------- main: fp16 1-pass mma, 512 threads, 128 pixels/CTA ----------------
__device__ __forceinline__ uint4 corner_ldh(const __half* __restrict__ xtbh, int y, int x, int c) {
    if ((unsigned)y < (unsigned)Hn && (unsigned)x < (unsigned)Wn)
        return *(const uint4*)(xtbh + (((y*Wn + x) << 8) + c));
    return make_uint4(0u, 0u, 0u, 0u);
}

__global__ __launch_bounds__(NT, 1) void main_kernel(float* __restrict__ out) {
    extern __shared__ char smc[];
    uint32_t sb = smem_u32(smc);
    float* spy = (float*)(smc + CO_B);
    float* spx = spy + NCOORD;
    float* smk = spx + NCOORD;

    int tid  = threadIdx.x;
    int lane = tid & 31;
    int wid  = tid >> 5;
    int pixb = blockIdx.x * TPIX;
    int b    = pixb / HWn;
    int hwb  = pixb % HWn;

    for (int i = tid; i < NCOORD; i += NT) {
        int p = i / KKn, k = i % KKn;
        int gi = (b*KKn + k)*HWn + hwb + p;
        spy[i] = g_py[gi]; spx[i] = g_px[gi]; smk[i] = g_msk[gi];
    }
    __syncthreads();

    const __half* xtbh = g_xth + (size_t)b * (HWn*Cn);

    int gp8 = tid >> 3;        // pixel (task0) 0..63; task1 pixel = gp8 + 64
    int gg  = tid & 7;         // 16B channel group (0..7 across 64 ch)
    uint32_t sts_sub = (uint32_t)(gg >> 2) * SSUB;
    uint32_t sts_off0 = sts_sub + (uint32_t)gp8*64u
                      + (uint32_t)(((gg & 3) ^ ((gp8 >> 1) & 3)) << 4);
    uint32_t sts_off1 = sts_sub + (uint32_t)(gp8 + 64)*64u
                      + (uint32_t)(((gg & 3) ^ (((gp8 + 64) >> 1) & 3)) << 4);

    auto cpW = [&](int q) {
        uint32_t wb = (q & 1) ? WH1 : WH0;
        #pragma unroll
        for (int i = 0; i < 4; i++) {
            int id = i*NT + tid;
            int o = id >> 3;
            int g = id & 7;
            const __half* src = g_wh + (size_t)o*KDIM + q*CH + g*8;
            uint32_t dst = sb + wb + (uint32_t)(g >> 2)*WSUB + (uint32_t)o*64u
                         + (uint32_t)(((g & 3) ^ ((o >> 1) & 3)) << 4);
            cp16(dst, src);
        }
        CP_COMMIT();
    };

    __half2 W00, W01, W10, W11, MMh;
    auto load_state = [&](int p, int kkn) {
        float py = spy[p*KKn + kkn], px = spx[p*KKn + kkn], mm = smk[p*KKn + kkn];
        float fy = floorf(py), fx = floorf(px);
        int y0 = (int)fy, x0 = (int)fx;
        float wy = py - fy, wx = px - fx;
        W00 = __float2half2_rn((1.f-wy)*(1.f-wx));
        W01 = __float2half2_rn((1.f-wy)*wx);
        W10 = __float2half2_rn(wy*(1.f-wx));
        W11 = __float2half2_rn(wy*wx);
        MMh = __float2half2_rn(mm);
        return make_int2(y0, x0);
    };
    auto interp_h2 = [&](uint4 C0, uint4 C1, uint4 C2, uint4 C3) -> uint4 {
        const __half2* c0 = (const __half2*)&C0;
        const __half2* c1 = (const __half2*)&C1;
        const __half2* c2 = (const __half2*)&C2;
        const __half2* c3 = (const __half2*)&C3;
        uint4 res;
        __half2* rp = (__half2*)&res;
        #pragma unroll
        for (int j = 0; j < 4; j++) {
            __half2 a = __hmul2(c0[j], W00);
            a = __hfma2(c1[j], W01, a);
            a = __hfma2(c2[j], W10, a);
            a = __hfma2(c3[j], W11, a);
            rp[j] = __hmul2(a, MMh);
        }
        return res;
    };

    // ---- prologue: w chunk 0 + full gather of s chunk 0 ----
    {
        cpW(0);
        int cb = gg*8;
        int2 yx = load_state(gp8, 0);
        uint4 C0 = corner_ldh(xtbh, yx.x,   yx.y,   cb);
        uint4 C1 = corner_ldh(xtbh, yx.x,   yx.y+1, cb);
        uint4 C2 = corner_ldh(xtbh, yx.x+1, yx.y,   cb);
        uint4 C3 = corner_ldh(xtbh, yx.x+1, yx.y+1, cb);
        *(uint4*)(smc + SH0 + sts_off0) = interp_h2(C0, C1, C2, C3);
        yx = load_state(gp8 + 64, 0);
        C0 = corner_ldh(xtbh, yx.x,   yx.y,   cb);
        C1 = corner_ldh(xtbh, yx.x,   yx.y+1, cb);
        C2 = corner_ldh(xtbh, yx.x+1, yx.y,   cb);
        C3 = corner_ldh(xtbh, yx.x+1, yx.y+1, cb);
        *(uint4*)(smc + SH0 + sts_off1) = interp_h2(C0, C1, C2, C3);
    }

    int ob = (wid >> 2) * 64;     // 4 o-groups of 64
    int pb = (wid & 3) * 32;      // 4 p-groups of 32 (128 pixels)
    float acc[4][4][4];
    #pragma unroll
    for (int mt = 0; mt < 4; mt++)
        #pragma unroll
        for (int nt = 0; nt < 4; nt++)
            #pragma unroll
            for (int e = 0; e < 4; e++) acc[mt][nt][e] = 0.f;

    #pragma unroll 1
    for (int q = 0; q < NCH2; q++) {
        int buf = q & 1;
        bool more = (q + 1 < NCH2);
        int kkn = (q + 1) >> 2;
        int cb  = ((q + 1) & 3) * 64 + gg*8;

        // ---- task0 pre-issue ----
        uint4 C0, C1, C2, C3;
        if (more) {
            int2 yx = load_state(gp8, kkn);
            C0 = corner_ldh(xtbh, yx.x,   yx.y,   cb);
            C1 = corner_ldh(xtbh, yx.x,   yx.y+1, cb);
            C2 = corner_ldh(xtbh, yx.x+1, yx.y,   cb);
            C3 = corner_ldh(xtbh, yx.x+1, yx.y+1, cb);
        }

        CP_WAIT0();
        __syncthreads();

        if (more) cpW(q+1);

        uint32_t whb = sb + (buf ? WH1 : WH0);
        uint32_t shb = sb + (buf ? SH1 : SH0);
        uint32_t sdst_b = ((q+1) & 1) ? SH1 : SH0;

        // ---- MMA sub-tile 0 (first 32 ch) ----
        #pragma unroll
        for (int ks2 = 0; ks2 < 2; ks2++) {
            int uu = ks2 * 2;
            uint32_t bh[2][4];
            #pragma unroll
            for (int np = 0; np < 2; np++) {
                int p = pb + np*16 + (lane & 7) + ((lane >> 4) << 3);
                int u = uu + ((lane >> 3) & 1);
                ldsm4(bh[np], shb + (uint32_t)p*64u + (uint32_t)((u ^ ((p>>1)&3)) << 4));
            }
            #pragma unroll
            for (int mt = 0; mt < 4; mt++) {
                int o = ob + mt*16 + (lane & 15);
                int u = uu + (lane >> 4);
                uint32_t ah[4];
                ldsm4(ah, whb + (uint32_t)o*64u + (uint32_t)((u ^ ((o>>1)&3)) << 4));
                #pragma unroll
                for (int np = 0; np < 2; np++)
                    #pragma unroll
                    for (int hf = 0; hf < 2; hf++)
                        mma_h(acc[mt][np*2+hf], ah, bh[np][hf*2], bh[np][hf*2+1]);
            }
        }

        // ---- finish task0; pre-issue task1 ----
        if (more) {
            *(uint4*)(smc + sdst_b + sts_off0) = interp_h2(C0, C1, C2, C3);
            int2 yx = load_state(gp8 + 64, kkn);
            C0 = corner_ldh(xtbh, yx.x,   yx.y,   cb);
            C1 = corner_ldh(xtbh, yx.x,   yx.y+1, cb);
            C2 = corner_ldh(xtbh, yx.x+1, yx.y,   cb);
            C3 = corner_ldh(xtbh, yx.x+1, yx.y+1, cb);
        }

        // ---- MMA sub-tile 1 (second 32 ch) ----
        #pragma unroll
        for (int ks2 = 0; ks2 < 2; ks2++) {
            int uu = ks2 * 2;
            uint32_t bh[2][4];
            #pragma unroll
            for (int np = 0; np < 2; np++) {
                int p = pb + np*16 + (lane & 7) + ((lane >> 4) << 3);
                int u = uu + ((lane >> 3) & 1);
                ldsm4(bh[np], shb + SSUB + (uint32_t)p*64u + (uint32_t)((u ^ ((p>>1)&3)) << 4));
            }
            #pragma unroll
            for (int mt = 0; mt < 4; mt++) {
                int o = ob + mt*16 + (lane & 15);
                int u = uu + (lane >> 4);
                uint32_t ah[4];
                ldsm4(ah, whb + WSUB + (uint32_t)o*64u + (uint32_t)((u ^ ((o>>1)&3)) << 4));
                #pragma unroll
                for (int np = 0; np < 2; np++)
                    #pragma unroll
                    for (int hf = 0; hf < 2; hf++)
                        mma_h(acc[mt][np*2+hf], ah, bh[np][hf*2], bh[np][hf*2+1]);
            }
        }

        // ---- finish task1 ----
        if (more) {
            *(uint4*)(smc + sdst_b + sts_off1) = interp_h2(C0, C1, C2, C3);
        }
    }

    // ---- epilogue: BN + ReLU ----
    int tg = lane & 3, g = lane >> 2;
    #pragma unroll
    for (int mt = 0; mt < 4; mt++) {
        int o0 = ob + mt*16 + g;
        int o1 = o0 + 8;
        float A0 = g_bnA[o0], B0 = g_bnB[o0];
        float A1 = g_bnA[o1], B1 = g_bnB[o1];
        float* r0 = out + ((size_t)(b*On + o0))*HWn + hwb;
        float* r1 = out + ((size_t)(b*On + o1))*HWn + hwb;
        #pragma unroll
        for (int nt = 0; nt < 4; nt++) {
            int p0 = pb + nt*8 + tg*2;
            float2 v0, v1;
            v0.x = fmaxf(acc[mt][nt][0]*A0 + B0, 0.f);
            v0.y = fmaxf(acc[mt][nt][1]*A0 + B0, 0.f);
            v1.x = fmaxf(acc[mt][nt][2]*A1 + B1, 0.f);
            v1.y = fmaxf(acc[mt][nt][3]*A1 + B1, 0.f);
            *(float2*)(r0 + p0) = v0;
            *(float2*)(r1 + p0) = v1;
        }
    }
}

// ---------------- launch ----------------
extern "C" void kernel_launch(void* const* d_in, const int* in_sizes, int n_in,
                              void* d_out, int out_size) {
    const float* x      = (const float*)d_in[0];
    const float* w_off  = (const float*)d_in[1];
    const float* b_off  = (const float*)d_in[2];
    const float* w_dcn  = (const float*)d_in[3];
    const float* b_dcn  = (const float*)d_in[4];
    const float* gamma  = (const float*)d_in[5];
    const float* beta   = (const float*)d_in[6];
    const float* rmean  = (const float*)d_in[7];
    const float* rvar   = (const float*)d_in[8];
    float* out = (float*)d_out;

    cudaFuncSetAttribute(main_kernel, cudaFuncAttributeMaxDynamicSharedMemorySize, SMEM_BYTES);
    cudaFuncSetAttribute(main_kernel, cudaFuncAttributePreferredSharedMemoryCarveout, 100);
    cudaFuncSetAttribute(offset_mma_kernel, cudaFuncAttributeMaxDynamicSharedMemorySize, OSMEM);

    prep_kernel<<<256, 256>>>(w_off, w_dcn, b_dcn, gamma, beta, rmean, rvar);

    dim3 tgrid(Wn/32, Cn/32, Bn*Hn);
    transpose_kernel<<<tgrid, dim3(32, 8)>>>(x);

    offset_mma_kernel<<<(Bn*HWn)/OTP, ONT, OSMEM>>>(b_off);

    main_kernel<<<(Bn*HWn)/TPIX, NT, SMEM_BYTES>>>(out);
}